// round 2
// baseline (speedup 1.0000x reference)
#include <cuda_runtime.h>
#include <cuda_bf16.h>

#define B_    64
#define S_    512
#define H_    1024
#define HID_  512
#define K3_   3072   // 3*H
#define EPS_  1e-5f
#define NCHUNK 8     // row chunks per span (512/64)
#define CHROWS 64    // rows per chunk

// Scratch (device globals: allocation-free)
__device__ int   g_off[B_ * 5];                // normalized int32 offsets
__device__ float g_sp[B_ * 2 * NCHUNK * H_];   // span partial sums      (4 MB)
__device__ float g_x [B_ * K3_];               // concat embeddings      (768 KB)
__device__ float g_hp[64 * B_ * HID_];         // GEMM partial slabs     (8 MB)

// ---------------------------------------------------------------------------
// Kernel 0: normalize offsets. Handles both int32 and int64 source data.
// If source is int64 (values < 512), every odd 32-bit word of the first 320
// words is 0; if int32, odd words are random span indices (never all zero).
// One block, 320 threads.
// ---------------------------------------------------------------------------
__global__ void decode_off(const unsigned int* __restrict__ raw) {
    __shared__ int not64;
    int t = threadIdx.x;                      // 0..319
    if (t == 0) not64 = 0;
    __syncthreads();
    if ((t & 1) && raw[t] != 0u) atomicExch(&not64, 1);
    __syncthreads();
    g_off[t] = not64 ? (int)raw[t] : (int)raw[2 * t];
}

// ---------------------------------------------------------------------------
// Kernel 1: partial span sums.
// grid (B, 2 spans, NCHUNK row-chunks), 256 threads, float4 per thread.
// ---------------------------------------------------------------------------
__global__ void span_partial(const float* __restrict__ bert) {
    int b  = blockIdx.x;
    int sp = blockIdx.y;
    int z  = blockIdx.z;
    int s0 = g_off[b * 5 + sp * 2];
    int s1 = g_off[b * 5 + sp * 2 + 1];
    int lo = max(s0, z * CHROWS);
    int hi = min(s1, z * CHROWS + CHROWS - 1);

    int t = threadIdx.x;               // 0..255
    float4 acc = make_float4(0.f, 0.f, 0.f, 0.f);

    const float* base = bert + ((size_t)b * S_) * H_ + 4 * t;
    for (int s = lo; s <= hi; ++s) {
        float4 v = *(const float4*)(base + (size_t)s * H_);
        acc.x += v.x; acc.y += v.y; acc.z += v.z; acc.w += v.w;
    }
    float* dst = g_sp + ((size_t)((b * 2 + sp) * NCHUNK + z)) * H_ + 4 * t;
    *(float4*)dst = acc;
}

// ---------------------------------------------------------------------------
// Kernel 2: reduce chunks -> means, gather pronoun row. grid(B), 1024 threads.
// ---------------------------------------------------------------------------
__global__ void finalize_x(const float* __restrict__ bert) {
    int b = blockIdx.x;
    int h = threadIdx.x;               // 0..1023
    int a0 = g_off[b * 5 + 0], a1 = g_off[b * 5 + 1];
    int c0 = g_off[b * 5 + 2], c1 = g_off[b * 5 + 3];
    int p  = g_off[b * 5 + 4];
    float inva = 1.0f / (float)(a1 - a0 + 1);
    float invb = 1.0f / (float)(c1 - c0 + 1);

    float sa = 0.f, sb = 0.f;
    #pragma unroll
    for (int z = 0; z < NCHUNK; ++z) {
        sa += g_sp[((size_t)((b * 2 + 0) * NCHUNK + z)) * H_ + h];
        sb += g_sp[((size_t)((b * 2 + 1) * NCHUNK + z)) * H_ + h];
    }
    float* xr = g_x + (size_t)b * K3_;
    xr[h]            = sa * inva;
    xr[H_ + h]       = sb * invb;
    xr[2 * H_ + h]   = bert[((size_t)b * S_ + p) * H_ + h];
}

// ---------------------------------------------------------------------------
// Kernel 3: GEMM x(64x3072) @ W1(3072x512) -> 64 partial slabs of (64x512).
// grid(8 j-tiles, 16 k-chunks), 256 threads = 64 j x 4 k-subchunks of 48.
// Each thread: acc[64] over all batches; xs broadcast from smem as float4.
// W1 read exactly once from DRAM total.
// ---------------------------------------------------------------------------
__global__ void gemm1(const float* __restrict__ W1) {
    __shared__ float xs[B_ * 192];     // 48 KB
    int jt  = blockIdx.x;              // 0..7
    int kt  = blockIdx.y;              // 0..15
    int tid = threadIdx.x;             // 0..255
    int jj  = tid & 63;
    int kk  = tid >> 6;                // 0..3
    int j   = jt * 64 + jj;
    int k0  = kt * 192;

    // cooperative load of x tile [64][192] (float4, coalesced)
    for (int i = tid; i < B_ * 192 / 4; i += 256) {
        int e  = i * 4;
        int m  = e / 192;
        int kl = e % 192;
        *(float4*)&xs[m * 192 + kl] =
            *(const float4*)&g_x[(size_t)m * K3_ + k0 + kl];
    }
    __syncthreads();

    float acc[B_];
    #pragma unroll
    for (int m = 0; m < B_; ++m) acc[m] = 0.f;

    int kbase = kk * 48;
    #pragma unroll 4
    for (int kq = 0; kq < 48; kq += 4) {
        int k = k0 + kbase + kq;
        float w0 = W1[(size_t)(k + 0) * HID_ + j];
        float w1 = W1[(size_t)(k + 1) * HID_ + j];
        float w2 = W1[(size_t)(k + 2) * HID_ + j];
        float w3 = W1[(size_t)(k + 3) * HID_ + j];
        #pragma unroll
        for (int m = 0; m < B_; ++m) {
            float4 xv = *(const float4*)&xs[m * 192 + kbase + kq];
            float a = acc[m];
            a = fmaf(xv.x, w0, a);
            a = fmaf(xv.y, w1, a);
            a = fmaf(xv.z, w2, a);
            a = fmaf(xv.w, w3, a);
            acc[m] = a;
        }
    }

    float* dst = g_hp + (size_t)(kt * 4 + kk) * B_ * HID_;
    #pragma unroll
    for (int m = 0; m < B_; ++m)
        dst[(size_t)m * HID_ + j] = acc[m];
}

// ---------------------------------------------------------------------------
// Kernel 4: reduce 64 partial slabs, BN + leaky, @W2 + b2 -> out[64][3].
// grid(B), 512 threads (one per hidden unit).
// ---------------------------------------------------------------------------
__global__ void head(const float* __restrict__ b1,
                     const float* __restrict__ gamma,
                     const float* __restrict__ beta,
                     const float* __restrict__ rmean,
                     const float* __restrict__ rvar,
                     const float* __restrict__ W2,
                     const float* __restrict__ b2,
                     float* __restrict__ out) {
    int b = blockIdx.x;
    int j = threadIdx.x;               // 0..511

    float s = 0.f;
    #pragma unroll
    for (int p = 0; p < 64; ++p)
        s += g_hp[(size_t)p * B_ * HID_ + (size_t)b * HID_ + j];

    float sc = gamma[j] * rsqrtf(rvar[j] + EPS_);
    float h  = (s + b1[j] - rmean[j]) * sc + beta[j];
    h = (h >= 0.f) ? h : 0.01f * h;

    float o0 = h * W2[j * 3 + 0];
    float o1 = h * W2[j * 3 + 1];
    float o2 = h * W2[j * 3 + 2];

    #pragma unroll
    for (int d = 16; d > 0; d >>= 1) {
        o0 += __shfl_down_sync(0xFFFFFFFFu, o0, d);
        o1 += __shfl_down_sync(0xFFFFFFFFu, o1, d);
        o2 += __shfl_down_sync(0xFFFFFFFFu, o2, d);
    }

    __shared__ float red[16][3];
    if ((j & 31) == 0) {
        int w = j >> 5;
        red[w][0] = o0; red[w][1] = o1; red[w][2] = o2;
    }
    __syncthreads();
    if (j < 3) {
        float t = 0.f;
        #pragma unroll
        for (int w = 0; w < 16; ++w) t += red[w][j];
        out[b * 3 + j] = t + b2[j];
    }
}

// ---------------------------------------------------------------------------
extern "C" void kernel_launch(void* const* d_in, const int* in_sizes, int n_in,
                              void* d_out, int out_size) {
    const float*        bert  = (const float*)d_in[0];
    const unsigned int* offw  = (const unsigned int*)d_in[1];
    const float*        W1    = (const float*)d_in[2];
    const float*        b1    = (const float*)d_in[3];
    const float*        gamma = (const float*)d_in[4];
    const float*        beta  = (const float*)d_in[5];
    const float*        rmean = (const float*)d_in[6];
    const float*        rvar  = (const float*)d_in[7];
    const float*        W2    = (const float*)d_in[8];
    const float*        b2    = (const float*)d_in[9];
    float* out = (float*)d_out;

    decode_off<<<1, B_ * 5>>>(offw);
    span_partial<<<dim3(B_, 2, NCHUNK), 256>>>(bert);
    finalize_x<<<B_, 1024>>>(bert);
    gemm1<<<dim3(8, 16), 256>>>(W1);
    head<<<B_, 512>>>(b1, gamma, beta, rmean, rvar, W2, b2, out);
}

// round 3
// speedup vs baseline: 1.0471x; 1.0471x over previous
#include <cuda_runtime.h>
#include <cuda_bf16.h>
#include <cstdint>

#define B_    64
#define S_    512
#define H_    1024
#define HID_  512
#define K3_   3072   // 3*H
#define EPS_  1e-5f
#define NCHUNK 8     // row chunks per span (512/64)
#define CHROWS 64    // rows per chunk
#define KC_   48     // k-chunk per gemm block
#define KT_   64     // number of k-chunks (KC_*KT_ = 3072)

// Scratch (device globals: allocation-free)
__device__ int   g_off[B_ * 5];                // normalized int32 offsets
__device__ float g_sp[B_ * 2 * NCHUNK * H_];   // span partial sums      (4 MB)
__device__ float g_x [B_ * K3_];               // concat embeddings      (768 KB)
__device__ float g_hp[KT_ * B_ * HID_];        // GEMM partial slabs     (8 MB)

// ---------------------------------------------------------------------------
// Kernel 0: normalize offsets (auto-detect int64 vs int32 source).
// ---------------------------------------------------------------------------
__global__ void decode_off(const unsigned int* __restrict__ raw) {
    __shared__ int not64;
    int t = threadIdx.x;                      // 0..319
    if (t == 0) not64 = 0;
    __syncthreads();
    if ((t & 1) && raw[t] != 0u) atomicExch(&not64, 1);
    __syncthreads();
    g_off[t] = not64 ? (int)raw[t] : (int)raw[2 * t];
}

// ---------------------------------------------------------------------------
// Kernel 1: partial span sums. grid (B, 2, NCHUNK), 256 thr, float4/thread.
// ---------------------------------------------------------------------------
__global__ void span_partial(const float* __restrict__ bert) {
    int b  = blockIdx.x;
    int sp = blockIdx.y;
    int z  = blockIdx.z;
    int s0 = g_off[b * 5 + sp * 2];
    int s1 = g_off[b * 5 + sp * 2 + 1];
    int lo = max(s0, z * CHROWS);
    int hi = min(s1, z * CHROWS + CHROWS - 1);

    int t = threadIdx.x;
    float4 acc = make_float4(0.f, 0.f, 0.f, 0.f);
    const float* base = bert + ((size_t)b * S_) * H_ + 4 * t;
    for (int s = lo; s <= hi; ++s) {
        float4 v = *(const float4*)(base + (size_t)s * H_);
        acc.x += v.x; acc.y += v.y; acc.z += v.z; acc.w += v.w;
    }
    float* dst = g_sp + ((size_t)((b * 2 + sp) * NCHUNK + z)) * H_ + 4 * t;
    *(float4*)dst = acc;
}

// ---------------------------------------------------------------------------
// Kernel 2: reduce chunks -> means, gather pronoun row. grid(B), 1024 thr.
// ---------------------------------------------------------------------------
__global__ void finalize_x(const float* __restrict__ bert) {
    int b = blockIdx.x;
    int h = threadIdx.x;
    int a0 = g_off[b * 5 + 0], a1 = g_off[b * 5 + 1];
    int c0 = g_off[b * 5 + 2], c1 = g_off[b * 5 + 3];
    int p  = g_off[b * 5 + 4];
    float inva = 1.0f / (float)(a1 - a0 + 1);
    float invb = 1.0f / (float)(c1 - c0 + 1);

    float sa = 0.f, sb = 0.f;
    #pragma unroll
    for (int z = 0; z < NCHUNK; ++z) {
        sa += g_sp[((size_t)((b * 2 + 0) * NCHUNK + z)) * H_ + h];
        sb += g_sp[((size_t)((b * 2 + 1) * NCHUNK + z)) * H_ + h];
    }
    float* xr = g_x + (size_t)b * K3_;
    xr[h]            = sa * inva;
    xr[H_ + h]       = sb * invb;
    xr[2 * H_ + h]   = bert[((size_t)b * S_ + p) * H_ + h];
}

// ---------------------------------------------------------------------------
// Kernel 3: GEMM x(64x3072) @ W1(3072x512) -> KT_ partial slabs (64x512).
// grid(2 jt x 64 kt), 256 threads. Block tile 64m x 256j x 48k.
// Thread tile 8m x 8j, accumulators packed as f32x2 along j (FFMA2 = 2x rate).
// x reads are warp-uniform (smem broadcast); w reads conflict-free.
// ---------------------------------------------------------------------------
__global__ void __launch_bounds__(256, 1) gemm1(const float* __restrict__ W1) {
    extern __shared__ float sm[];
    float* xs = sm;                 // [KC_][64]   12 KB
    float* ws = sm + KC_ * 64;      // [KC_][256]  48 KB

    int jt  = blockIdx.x;           // 0..1
    int kt  = blockIdx.y;           // 0..63
    int tid = threadIdx.x;
    int jg  = tid & 31;             // j-group within block tile (x8)
    int mg  = tid >> 5;             // m-group = warp id (x8)
    int k0  = kt * KC_;
    int jb  = jt * 256;

    // load W1 tile [KC_][256] (coalesced float4)
    for (int i = tid; i < KC_ * 64; i += 256) {
        int r = i >> 6, c = (i & 63) << 2;
        *(float4*)&ws[r * 256 + c] =
            *(const float4*)&W1[(size_t)(k0 + r) * HID_ + jb + c];
    }
    // load x tile transposed: g_x[m][k0+k] -> xs[k][m]
    for (int i = tid; i < 64 * (KC_ / 4); i += 256) {
        int m = i / (KC_ / 4), kq = i % (KC_ / 4);
        float4 v = *(const float4*)&g_x[(size_t)m * K3_ + k0 + kq * 4];
        xs[(kq * 4 + 0) * 64 + m] = v.x;
        xs[(kq * 4 + 1) * 64 + m] = v.y;
        xs[(kq * 4 + 2) * 64 + m] = v.z;
        xs[(kq * 4 + 3) * 64 + m] = v.w;
    }
    __syncthreads();

    int m0 = mg * 8;
    int j0 = jg * 8;

    unsigned long long acc[8][4];   // [m][j-pair], f32x2 packed {j even, j odd}
    #pragma unroll
    for (int m = 0; m < 8; ++m)
        #pragma unroll
        for (int q = 0; q < 4; ++q) acc[m][q] = 0ull;

    uint32_t ws_addr = (uint32_t)__cvta_generic_to_shared(ws + j0);
    const float* xrow = xs + m0;

    #pragma unroll 4
    for (int k = 0; k < KC_; ++k) {
        // w: 8 consecutive j as 4 f32x2 (two 16B shared loads)
        unsigned long long w0, w1, w2, w3;
        uint32_t wa = ws_addr + (uint32_t)(k * 256 * 4);
        asm volatile("ld.shared.v2.u64 {%0,%1}, [%2];"
                     : "=l"(w0), "=l"(w1) : "r"(wa));
        asm volatile("ld.shared.v2.u64 {%0,%1}, [%2];"
                     : "=l"(w2), "=l"(w3) : "r"(wa + 16));
        // x: 8 floats (warp-uniform -> broadcast)
        float4 xa = *(const float4*)(xrow + k * 64);
        float4 xb = *(const float4*)(xrow + k * 64 + 4);
        float xv[8] = {xa.x, xa.y, xa.z, xa.w, xb.x, xb.y, xb.z, xb.w};
        #pragma unroll
        for (int m = 0; m < 8; ++m) {
            unsigned long long xd;
            asm volatile("mov.b64 %0, {%1, %1};" : "=l"(xd) : "f"(xv[m]));
            asm volatile("fma.rn.f32x2 %0, %1, %2, %0;"
                         : "+l"(acc[m][0]) : "l"(w0), "l"(xd));
            asm volatile("fma.rn.f32x2 %0, %1, %2, %0;"
                         : "+l"(acc[m][1]) : "l"(w1), "l"(xd));
            asm volatile("fma.rn.f32x2 %0, %1, %2, %0;"
                         : "+l"(acc[m][2]) : "l"(w2), "l"(xd));
            asm volatile("fma.rn.f32x2 %0, %1, %2, %0;"
                         : "+l"(acc[m][3]) : "l"(w3), "l"(xd));
        }
    }

    float* dst = g_hp + (size_t)kt * B_ * HID_;
    #pragma unroll
    for (int m = 0; m < 8; ++m) {
        unsigned long long* row =
            (unsigned long long*)&dst[(size_t)(m0 + m) * HID_ + jb + j0];
        row[0] = acc[m][0];
        row[1] = acc[m][1];
        row[2] = acc[m][2];
        row[3] = acc[m][3];
    }
}

// ---------------------------------------------------------------------------
// Kernel 4: reduce KT_ slabs, BN + leaky, @W2 + b2 -> out[64][3].
// ---------------------------------------------------------------------------
__global__ void head(const float* __restrict__ b1,
                     const float* __restrict__ gamma,
                     const float* __restrict__ beta,
                     const float* __restrict__ rmean,
                     const float* __restrict__ rvar,
                     const float* __restrict__ W2,
                     const float* __restrict__ b2,
                     float* __restrict__ out) {
    int b = blockIdx.x;
    int j = threadIdx.x;               // 0..511

    float s = 0.f;
    #pragma unroll
    for (int p = 0; p < KT_; ++p)
        s += g_hp[(size_t)p * B_ * HID_ + (size_t)b * HID_ + j];

    float sc = gamma[j] * rsqrtf(rvar[j] + EPS_);
    float h  = (s + b1[j] - rmean[j]) * sc + beta[j];
    h = (h >= 0.f) ? h : 0.01f * h;

    float o0 = h * W2[j * 3 + 0];
    float o1 = h * W2[j * 3 + 1];
    float o2 = h * W2[j * 3 + 2];

    #pragma unroll
    for (int d = 16; d > 0; d >>= 1) {
        o0 += __shfl_down_sync(0xFFFFFFFFu, o0, d);
        o1 += __shfl_down_sync(0xFFFFFFFFu, o1, d);
        o2 += __shfl_down_sync(0xFFFFFFFFu, o2, d);
    }

    __shared__ float red[16][3];
    if ((j & 31) == 0) {
        int w = j >> 5;
        red[w][0] = o0; red[w][1] = o1; red[w][2] = o2;
    }
    __syncthreads();
    if (j < 3) {
        float t = 0.f;
        #pragma unroll
        for (int w = 0; w < 16; ++w) t += red[w][j];
        out[b * 3 + j] = t + b2[j];
    }
}

// ---------------------------------------------------------------------------
extern "C" void kernel_launch(void* const* d_in, const int* in_sizes, int n_in,
                              void* d_out, int out_size) {
    const float*        bert  = (const float*)d_in[0];
    const unsigned int* offw  = (const unsigned int*)d_in[1];
    const float*        W1    = (const float*)d_in[2];
    const float*        b1    = (const float*)d_in[3];
    const float*        gamma = (const float*)d_in[4];
    const float*        beta  = (const float*)d_in[5];
    const float*        rmean = (const float*)d_in[6];
    const float*        rvar  = (const float*)d_in[7];
    const float*        W2    = (const float*)d_in[8];
    const float*        b2    = (const float*)d_in[9];
    float* out = (float*)d_out;

    const int gemm_smem = (KC_ * 64 + KC_ * 256) * (int)sizeof(float); // 60 KB
    cudaFuncSetAttribute(gemm1, cudaFuncAttributeMaxDynamicSharedMemorySize,
                         gemm_smem);

    decode_off<<<1, B_ * 5>>>(offw);
    span_partial<<<dim3(B_, 2, NCHUNK), 256>>>(bert);
    finalize_x<<<B_, 1024>>>(bert);
    gemm1<<<dim3(2, KT_), 256, gemm_smem>>>(W1);
    head<<<B_, 512>>>(b1, gamma, beta, rmean, rvar, W2, b2, out);
}